// round 1
// baseline (speedup 1.0000x reference)
#include <cuda_runtime.h>
#include <math.h>
#include <limits.h>

#define LROW 2048
#define SDIM 65
#define OUT_PER_ROW (SDIM * SDIM)   // 4225
#define THRESH 0.2f
#define EPSV 1e-6f
#define NTHREADS 256

__global__ __launch_bounds__(NTHREADS, 8)
void rp_kernel(const float* __restrict__ x, float* __restrict__ out) {
    const int row = blockIdx.x;
    const int t = threadIdx.x;
    const float4* __restrict__ xr =
        reinterpret_cast<const float4*>(x + (size_t)row * LROW);

    // ---- one-pass row stats: sum, sumsq, min/max nonzero index ----
    float sum = 0.f, sumsq = 0.f;
    int mn = INT_MAX, mx = -1;
    #pragma unroll
    for (int it = 0; it < 2; it++) {
        const int q = t + it * NTHREADS;      // float4 index 0..511
        const float4 v = xr[q];
        sum   += (v.x + v.y) + (v.z + v.w);
        sumsq += (v.x * v.x + v.y * v.y) + (v.z * v.z + v.w * v.w);
        const int base = q * 4;
        if (v.x != 0.f) { mn = min(mn, base + 0); mx = max(mx, base + 0); }
        if (v.y != 0.f) { mn = min(mn, base + 1); mx = max(mx, base + 1); }
        if (v.z != 0.f) { mn = min(mn, base + 2); mx = max(mx, base + 2); }
        if (v.w != 0.f) { mn = min(mn, base + 3); mx = max(mx, base + 3); }
    }

    // ---- warp reduce ----
    #pragma unroll
    for (int o = 16; o > 0; o >>= 1) {
        sum   += __shfl_down_sync(0xffffffffu, sum, o);
        sumsq += __shfl_down_sync(0xffffffffu, sumsq, o);
        mn = min(mn, __shfl_down_sync(0xffffffffu, mn, o));
        mx = max(mx, __shfl_down_sync(0xffffffffu, mx, o));
    }

    __shared__ float s_sum[8], s_sq[8];
    __shared__ int   s_mn[8],  s_mx[8];
    const int wid = t >> 5, lid = t & 31;
    if (lid == 0) { s_sum[wid] = sum; s_sq[wid] = sumsq; s_mn[wid] = mn; s_mx[wid] = mx; }
    __syncthreads();

    __shared__ float s_mean, s_rstd;
    __shared__ int   s_start, s_end;
    if (t < 32) {
        sum   = (t < 8) ? s_sum[t] : 0.f;
        sumsq = (t < 8) ? s_sq[t]  : 0.f;
        mn    = (t < 8) ? s_mn[t]  : INT_MAX;
        mx    = (t < 8) ? s_mx[t]  : -1;
        #pragma unroll
        for (int o = 4; o > 0; o >>= 1) {
            sum   += __shfl_down_sync(0xffffffffu, sum, o);
            sumsq += __shfl_down_sync(0xffffffffu, sumsq, o);
            mn = min(mn, __shfl_down_sync(0xffffffffu, mn, o));
            mx = max(mx, __shfl_down_sync(0xffffffffu, mx, o));
        }
        if (t == 0) {
            const float cnt  = (mx >= 0) ? (float)(mx - mn + 1) : 1.f;
            const float mean = sum / cnt;
            const float var  = fmaxf(sumsq / cnt - mean * mean, 0.f);
            const float stdv = fmaxf(sqrtf(var), EPSV);
            s_mean = mean;
            s_rstd = 1.f / stdv;
            s_start = mn;   // INT_MAX if empty
            s_end   = mx;   // -1 if empty
        }
    }
    __syncthreads();

    // ---- normalized first 65 values; NaN sentinel encodes invalid mask ----
    __shared__ float ys[SDIM];
    if (t < SDIM) {
        const bool valid = (t >= s_start) && (t <= s_end);
        if (valid) {
            ys[t] = (x[(size_t)row * LROW + t] - s_mean) * s_rstd;
        } else {
            ys[t] = __int_as_float(0x7fffffff);  // NaN: any compare -> false -> 0
        }
    }
    __syncthreads();

    // ---- 65x65 proximity matrix, coalesced scalar stores ----
    float* __restrict__ orow = out + (size_t)row * OUT_PER_ROW;
    #pragma unroll 4
    for (int k = t; k < OUT_PER_ROW; k += NTHREADS) {
        const unsigned i = (unsigned)k / 65u;       // strength-reduced to umulhi
        const unsigned j = (unsigned)k - i * 65u;
        const float d = fabsf(ys[i] - ys[j]);
        orow[k] = (d < THRESH) ? 1.f : 0.f;         // NaN -> false -> 0
    }
}

extern "C" void kernel_launch(void* const* d_in, const int* in_sizes, int n_in,
                              void* d_out, int out_size) {
    const float* x = (const float*)d_in[0];
    float* out = (float*)d_out;
    const int nrows = in_sizes[0] / LROW;   // 1024*16 = 16384
    rp_kernel<<<nrows, NTHREADS>>>(x, out);
}

// round 2
// speedup vs baseline: 1.0468x; 1.0468x over previous
#include <cuda_runtime.h>
#include <math.h>
#include <limits.h>

#define LROW 2048
#define SDIM 65
#define OUT_PER_ROW (SDIM * SDIM)   // 4225
#define THRESH 0.2f
#define EPSV 1e-6f
#define NTHREADS 256

__global__ __launch_bounds__(NTHREADS, 8)
void rp_kernel(const float* __restrict__ x, float* __restrict__ out) {
    const int row = blockIdx.x;
    const int t = threadIdx.x;
    const float4* __restrict__ xr =
        reinterpret_cast<const float4*>(x + (size_t)row * LROW);

    // ---- one-pass row stats: sum, sumsq, min/max nonzero index ----
    // Streaming loads: touched exactly once.
    const float4 v0 = __ldcs(&xr[t]);            // covers idx 4t..4t+3 (t<17 holds first 68)
    const float4 v1 = __ldcs(&xr[t + NTHREADS]);

    float sum = 0.f, sumsq = 0.f;
    int mn = INT_MAX, mx = -1;
    {
        const float4 v = v0; const int base = t * 4;
        sum   += (v.x + v.y) + (v.z + v.w);
        sumsq += (v.x * v.x + v.y * v.y) + (v.z * v.z + v.w * v.w);
        if (v.x != 0.f) { mn = min(mn, base + 0); mx = max(mx, base + 0); }
        if (v.y != 0.f) { mn = min(mn, base + 1); mx = max(mx, base + 1); }
        if (v.z != 0.f) { mn = min(mn, base + 2); mx = max(mx, base + 2); }
        if (v.w != 0.f) { mn = min(mn, base + 3); mx = max(mx, base + 3); }
    }
    {
        const float4 v = v1; const int base = (t + NTHREADS) * 4;
        sum   += (v.x + v.y) + (v.z + v.w);
        sumsq += (v.x * v.x + v.y * v.y) + (v.z * v.z + v.w * v.w);
        if (v.x != 0.f) { mn = min(mn, base + 0); mx = max(mx, base + 0); }
        if (v.y != 0.f) { mn = min(mn, base + 1); mx = max(mx, base + 1); }
        if (v.z != 0.f) { mn = min(mn, base + 2); mx = max(mx, base + 2); }
        if (v.w != 0.f) { mn = min(mn, base + 3); mx = max(mx, base + 3); }
    }

    // ---- warp reduce ----
    #pragma unroll
    for (int o = 16; o > 0; o >>= 1) {
        sum   += __shfl_down_sync(0xffffffffu, sum, o);
        sumsq += __shfl_down_sync(0xffffffffu, sumsq, o);
        mn = min(mn, __shfl_down_sync(0xffffffffu, mn, o));
        mx = max(mx, __shfl_down_sync(0xffffffffu, mx, o));
    }

    __shared__ float s_sum[8], s_sq[8];
    __shared__ int   s_mn[8],  s_mx[8];
    const int wid = t >> 5, lid = t & 31;
    if (lid == 0) { s_sum[wid] = sum; s_sq[wid] = sumsq; s_mn[wid] = mn; s_mx[wid] = mx; }
    __syncthreads();

    __shared__ float s_mean, s_rstd;
    __shared__ int   s_start, s_end;
    if (t < 32) {
        sum   = (t < 8) ? s_sum[t] : 0.f;
        sumsq = (t < 8) ? s_sq[t]  : 0.f;
        mn    = (t < 8) ? s_mn[t]  : INT_MAX;
        mx    = (t < 8) ? s_mx[t]  : -1;
        #pragma unroll
        for (int o = 4; o > 0; o >>= 1) {
            sum   += __shfl_down_sync(0xffffffffu, sum, o);
            sumsq += __shfl_down_sync(0xffffffffu, sumsq, o);
            mn = min(mn, __shfl_down_sync(0xffffffffu, mn, o));
            mx = max(mx, __shfl_down_sync(0xffffffffu, mx, o));
        }
        if (t == 0) {
            const float cnt  = (mx >= 0) ? (float)(mx - mn + 1) : 1.f;
            const float mean = sum / cnt;
            const float var  = fmaxf(sumsq / cnt - mean * mean, 0.f);
            const float stdv = fmaxf(sqrtf(var), EPSV);
            s_mean = mean;
            s_rstd = 1.f / stdv;
            s_start = mn;   // INT_MAX if empty
            s_end   = mx;   // -1 if empty
        }
    }
    __syncthreads();

    // ---- normalized first 65 values from registers (no x re-read) ----
    // NaN sentinel encodes invalid: any compare with NaN -> false -> 0.
    __shared__ float ys[SDIM + 1];   // +1 pad so ys[i+1] prefetch is never OOB
    if (t < 17) {
        const float vals[4] = {v0.x, v0.y, v0.z, v0.w};
        const float mean = s_mean, rstd = s_rstd;
        const int st = s_start, en = s_end;
        #pragma unroll
        for (int e = 0; e < 4; e++) {
            const int idx = 4 * t + e;
            if (idx <= SDIM) {      // fill ys[65] pad too (value irrelevant)
                const bool valid = (idx >= st) && (idx <= en);
                ys[idx] = valid ? (vals[e] - mean) * rstd
                                : __int_as_float(0x7fffffff);
            }
        }
    }
    __syncthreads();

    // ---- 65x65 proximity matrix: STG.128 vector body + scalar head/tail ----
    float* __restrict__ orow = out + (size_t)row * OUT_PER_ROW;
    // float-index alignment: (row*4225 + k) % 4 == 0  <=>  k ≡ (-row) mod 4
    const int s = (4 - (row & 3)) & 3;          // head scalars
    const int m = (OUT_PER_ROW - s) >> 2;       // float4 groups
    const int tail = s + 4 * m;                 // first tail index

    if (t == 0) {                                // head (<=3 elems)
        for (int k = 0; k < s; k++) {
            const unsigned i = (unsigned)k / 65u;
            const unsigned j = (unsigned)k - i * 65u;
            const float d = fabsf(ys[i] - ys[j]);
            __stcs(&orow[k], (d < THRESH) ? 1.f : 0.f);
        }
    }
    if (t == 1) {                                // tail (<=3 elems)
        for (int k = tail; k < OUT_PER_ROW; k++) {
            const unsigned i = (unsigned)k / 65u;
            const unsigned j = (unsigned)k - i * 65u;
            const float d = fabsf(ys[i] - ys[j]);
            __stcs(&orow[k], (d < THRESH) ? 1.f : 0.f);
        }
    }

    #pragma unroll 2
    for (int g = t; g < m; g += NTHREADS) {
        const int k = s + 4 * g;                 // 16B-aligned global float index
        const unsigned i = (unsigned)k / 65u;
        const unsigned j = (unsigned)k - i * 65u;
        const float yi0 = ys[i];
        const float yi1 = ys[i + 1];             // pad makes this safe
        float4 o;
        {   // e = 0..3, at most one row-wrap within the group
            const unsigned j0 = j;
            o.x = (fabsf(yi0 - ys[j0]) < THRESH) ? 1.f : 0.f;
            const unsigned j1 = j + 1; const bool w1 = (j1 >= 65u);
            o.y = (fabsf((w1 ? yi1 : yi0) - ys[w1 ? j1 - 65u : j1]) < THRESH) ? 1.f : 0.f;
            const unsigned j2 = j + 2; const bool w2 = (j2 >= 65u);
            o.z = (fabsf((w2 ? yi1 : yi0) - ys[w2 ? j2 - 65u : j2]) < THRESH) ? 1.f : 0.f;
            const unsigned j3 = j + 3; const bool w3 = (j3 >= 65u);
            o.w = (fabsf((w3 ? yi1 : yi0) - ys[w3 ? j3 - 65u : j3]) < THRESH) ? 1.f : 0.f;
        }
        __stcs(reinterpret_cast<float4*>(&orow[k]), o);
    }
}

extern "C" void kernel_launch(void* const* d_in, const int* in_sizes, int n_in,
                              void* d_out, int out_size) {
    const float* x = (const float*)d_in[0];
    float* out = (float*)d_out;
    const int nrows = in_sizes[0] / LROW;   // 1024*16 = 16384
    rp_kernel<<<nrows, NTHREADS>>>(x, out);
}

// round 3
// speedup vs baseline: 1.0483x; 1.0014x over previous
#include <cuda_runtime.h>
#include <math.h>
#include <limits.h>

#define LROW 2048
#define SDIM 65
#define OUT_PER_ROW (SDIM * SDIM)   // 4225
#define THRESH 0.2f
#define EPSV 1e-6f
#define NTHREADS 256

__global__ __launch_bounds__(NTHREADS, 8)
void rp_kernel(const float* __restrict__ x, float* __restrict__ out) {
    const int row = blockIdx.x;
    const int t = threadIdx.x;
    const float4* __restrict__ xr =
        reinterpret_cast<const float4*>(x + (size_t)row * LROW);

    // ---- one-pass row stats: sum, sumsq, min/max nonzero index ----
    const float4 v0 = __ldcs(&xr[t]);            // idx 4t..4t+3 (t<17 holds first 68)
    const float4 v1 = __ldcs(&xr[t + NTHREADS]);

    float sum = 0.f, sumsq = 0.f;
    int mn = INT_MAX, mx = -1;
    {
        const float4 v = v0; const int base = t * 4;
        sum   += (v.x + v.y) + (v.z + v.w);
        sumsq += (v.x * v.x + v.y * v.y) + (v.z * v.z + v.w * v.w);
        if (v.x != 0.f) { mn = min(mn, base + 0); mx = max(mx, base + 0); }
        if (v.y != 0.f) { mn = min(mn, base + 1); mx = max(mx, base + 1); }
        if (v.z != 0.f) { mn = min(mn, base + 2); mx = max(mx, base + 2); }
        if (v.w != 0.f) { mn = min(mn, base + 3); mx = max(mx, base + 3); }
    }
    {
        const float4 v = v1; const int base = (t + NTHREADS) * 4;
        sum   += (v.x + v.y) + (v.z + v.w);
        sumsq += (v.x * v.x + v.y * v.y) + (v.z * v.z + v.w * v.w);
        if (v.x != 0.f) { mn = min(mn, base + 0); mx = max(mx, base + 0); }
        if (v.y != 0.f) { mn = min(mn, base + 1); mx = max(mx, base + 1); }
        if (v.z != 0.f) { mn = min(mn, base + 2); mx = max(mx, base + 2); }
        if (v.w != 0.f) { mn = min(mn, base + 3); mx = max(mx, base + 3); }
    }

    // ---- warp reduce ----
    #pragma unroll
    for (int o = 16; o > 0; o >>= 1) {
        sum   += __shfl_down_sync(0xffffffffu, sum, o);
        sumsq += __shfl_down_sync(0xffffffffu, sumsq, o);
        mn = min(mn, __shfl_down_sync(0xffffffffu, mn, o));
        mx = max(mx, __shfl_down_sync(0xffffffffu, mx, o));
    }

    __shared__ float s_sum[8], s_sq[8];
    __shared__ int   s_mn[8],  s_mx[8];
    const int wid = t >> 5, lid = t & 31;
    if (lid == 0) { s_sum[wid] = sum; s_sq[wid] = sumsq; s_mn[wid] = mn; s_mx[wid] = mx; }
    __syncthreads();

    __shared__ float s_mean, s_rstd;
    __shared__ int   s_start, s_end;
    if (t < 32) {
        sum   = (t < 8) ? s_sum[t] : 0.f;
        sumsq = (t < 8) ? s_sq[t]  : 0.f;
        mn    = (t < 8) ? s_mn[t]  : INT_MAX;
        mx    = (t < 8) ? s_mx[t]  : -1;
        #pragma unroll
        for (int o = 4; o > 0; o >>= 1) {
            sum   += __shfl_down_sync(0xffffffffu, sum, o);
            sumsq += __shfl_down_sync(0xffffffffu, sumsq, o);
            mn = min(mn, __shfl_down_sync(0xffffffffu, mn, o));
            mx = max(mx, __shfl_down_sync(0xffffffffu, mx, o));
        }
        if (t == 0) {
            const float cnt  = (mx >= 0) ? (float)(mx - mn + 1) : 1.f;
            const float mean = sum / cnt;
            const float var  = fmaxf(sumsq / cnt - mean * mean, 0.f);
            const float stdv = fmaxf(sqrtf(var), EPSV);
            s_mean = mean;
            s_rstd = 1.f / stdv;
            s_start = mn;
            s_end   = mx;
        }
    }
    __syncthreads();

    // ---- normalized first 65 values, DUPLICATED: ysd[m] = ys[m % 65], m<130 ----
    // NaN sentinel encodes invalid mask (any NaN compare -> false -> 0).
    __shared__ float ysd[132];       // 130 used + pad
    if (t < 17) {
        const float vals[4] = {v0.x, v0.y, v0.z, v0.w};
        const float mean = s_mean, rstd = s_rstd;
        const int st = s_start, en = s_end;
        #pragma unroll
        for (int e = 0; e < 4; e++) {
            const int idx = 4 * t + e;
            if (idx < SDIM) {
                const bool valid = (idx >= st) && (idx <= en);
                const float yv = valid ? (vals[e] - mean) * rstd
                                       : __int_as_float(0x7fffffff);
                ysd[idx] = yv;
                ysd[idx + SDIM] = yv;    // duplicate copy: no wrap arithmetic later
            }
        }
    }
    __syncthreads();

    // ---- 65x65 proximity matrix: STG.128 vector body + scalar head/tail ----
    float* __restrict__ orow = out + (size_t)row * OUT_PER_ROW;
    // global float-index alignment: k ≡ (-row*4225) ≡ (-row) mod 4
    const int s = (4 - (row & 3)) & 3;
    const int m = (OUT_PER_ROW - s) >> 2;
    const int tail = s + 4 * m;

    if (t == 0) {
        for (int k = 0; k < s; k++) {
            const unsigned i = (unsigned)k / 65u;
            const unsigned j = (unsigned)k - i * 65u;
            __stcs(&orow[k], (fabsf(ysd[i] - ysd[j]) < THRESH) ? 1.f : 0.f);
        }
    }
    if (t == 1) {
        for (int k = tail; k < OUT_PER_ROW; k++) {
            const unsigned i = (unsigned)k / 65u;
            const unsigned j = (unsigned)k - i * 65u;
            __stcs(&orow[k], (fabsf(ysd[i] - ysd[j]) < THRESH) ? 1.f : 0.f);
        }
    }

    #pragma unroll 4
    for (int g = t; g < m; g += NTHREADS) {
        const int k = s + 4 * g;                     // 16B-aligned global index
        const unsigned i = (unsigned)k / 65u;
        const unsigned j = (unsigned)k - i * 65u;    // 0..64
        const float yi0 = ysd[i];
        const float yi1 = ysd[i + 1];                // safe: i <= 64 -> ysd[65]
        const unsigned thr = 65u - j;                // e >= thr  <=> row wrap
        // a-side: duplicated array, unconditional loads, incremental addresses
        const float a0 = ysd[j];
        const float a1 = ysd[j + 1];
        const float a2 = ysd[j + 2];
        const float a3 = ysd[j + 3];
        float4 o;
        o.x = (fabsf(yi0 - a0) < THRESH) ? 1.f : 0.f;                     // e=0 < thr always
        o.y = (fabsf(((1u >= thr) ? yi1 : yi0) - a1) < THRESH) ? 1.f : 0.f;
        o.z = (fabsf(((2u >= thr) ? yi1 : yi0) - a2) < THRESH) ? 1.f : 0.f;
        o.w = (fabsf(((3u >= thr) ? yi1 : yi0) - a3) < THRESH) ? 1.f : 0.f;
        __stcs(reinterpret_cast<float4*>(&orow[k]), o);
    }
}

extern "C" void kernel_launch(void* const* d_in, const int* in_sizes, int n_in,
                              void* d_out, int out_size) {
    const float* x = (const float*)d_in[0];
    float* out = (float*)d_out;
    const int nrows = in_sizes[0] / LROW;   // 1024*16 = 16384
    rp_kernel<<<nrows, NTHREADS>>>(x, out);
}